// round 1
// baseline (speedup 1.0000x reference)
#include <cuda_runtime.h>

// VIN_68401649156499
// r = conv(input, w_eff) + b_eff   (w_eff = sum_c w_r[c] * w_h[c], collapsing 150-ch hidden)
// qr_a = conv(r, w_q[a])           (loop invariant, registers)
// v0 = max_a qr_a
// 79x: v = max_a (qr_a + conv(v, w_w[a]))     entirely in SMEM
// final q_a = qr_a + conv(v, w_w[a]); logits = q[b,:,sx,sy]

#define BH 66           // 64 + 2 halo
#define NPIX 4096

__device__ float g_weff[18];
__device__ float g_beff;

__global__ void prep_kernel(const float* __restrict__ w_h,
                            const float* __restrict__ b_h,
                            const float* __restrict__ w_r) {
    int t = threadIdx.x;
    if (t < 18) {
        float s = 0.f;
        for (int c = 0; c < 150; ++c) s += w_r[c] * w_h[c * 18 + t];
        g_weff[t] = s;
    } else if (t == 18) {
        float s = 0.f;
        for (int c = 0; c < 150; ++c) s += w_r[c] * b_h[c];
        g_beff = s;
    }
}

__global__ __launch_bounds__(512) void vin_kernel(
    const float* __restrict__ input,   // [128,2,64,64]
    const int*   __restrict__ coords,  // [128,4]
    const float* __restrict__ w_q,     // [5,1,3,3]
    const float* __restrict__ w_w,     // [5,1,3,3]
    float* __restrict__ out_q,         // [128,5,64,64]
    float* __restrict__ out_logits)    // [128,5]
{
    __shared__ float buf[2][BH * BH];

    const int b  = blockIdx.x;
    const int t  = threadIdx.x;
    const int y  = t >> 3;          // 0..63
    const int x0 = (t & 7) * 8;     // 0,8,...,56  (8 contiguous pixels per thread)

    // ---- zero both padded planes (halo must stay zero forever) ----
    for (int k = t; k < 2 * BH * BH; k += 512) (&buf[0][0])[k] = 0.f;
    __syncthreads();

    // ---- stage input (2 channels) into padded planes ----
    const float* inb = input + (size_t)b * 2 * NPIX;
    #pragma unroll
    for (int k = 0; k < 16; ++k) {
        int lin = k * 512 + t;              // 0..8191
        int li  = lin >> 12;
        int rem = lin & 4095;
        int yy  = rem >> 6;
        int xx  = rem & 63;
        buf[li][(yy + 1) * BH + xx + 1] = inb[lin];
    }
    __syncthreads();

    // ---- r = conv(input, w_eff) + b_eff  (into registers) ----
    float weff[18];
    #pragma unroll
    for (int k = 0; k < 18; ++k) weff[k] = g_weff[k];
    const float beff = g_beff;

    float rloc[8];
    #pragma unroll
    for (int i = 0; i < 8; ++i) {
        float s = beff;
        #pragma unroll
        for (int li = 0; li < 2; ++li)
            #pragma unroll
            for (int dy = 0; dy < 3; ++dy)
                #pragma unroll
                for (int dx = 0; dx < 3; ++dx)
                    s = fmaf(weff[li * 9 + dy * 3 + dx],
                             buf[li][(y + dy) * BH + x0 + i + dx], s);
        rloc[i] = s;
    }
    __syncthreads();

    // ---- store r into buf[1] interior (halo already zero) ----
    #pragma unroll
    for (int i = 0; i < 8; ++i) buf[1][(y + 1) * BH + x0 + i + 1] = rloc[i];
    __syncthreads();

    // ---- qr_a = conv(r, w_q[a])  (registers, loop invariant) ----
    float wq[45];
    #pragma unroll
    for (int k = 0; k < 45; ++k) wq[k] = w_q[k];

    float qr[5][8];
    #pragma unroll
    for (int i = 0; i < 8; ++i) {
        #pragma unroll
        for (int a = 0; a < 5; ++a) {
            float s = 0.f;
            #pragma unroll
            for (int dy = 0; dy < 3; ++dy)
                #pragma unroll
                for (int dx = 0; dx < 3; ++dx)
                    s = fmaf(wq[a * 9 + dy * 3 + dx],
                             buf[1][(y + dy) * BH + x0 + i + dx], s);
            qr[a][i] = s;
        }
    }

    // ---- v0 = max_a qr_a  -> buf[0] ----
    #pragma unroll
    for (int i = 0; i < 8; ++i) {
        float v = qr[0][i];
        #pragma unroll
        for (int a = 1; a < 5; ++a) v = fmaxf(v, qr[a][i]);
        buf[0][(y + 1) * BH + x0 + i + 1] = v;
    }

    float ww[45];
    #pragma unroll
    for (int k = 0; k < 45; ++k) ww[k] = w_w[k];
    __syncthreads();

    // ---- 79 Bellman iterations, double-buffered in SMEM ----
    for (int it = 0; it < 79; ++it) {
        const float* vi = buf[it & 1];
        float*       vo = buf[1 - (it & 1)];
        #pragma unroll
        for (int i = 0; i < 8; ++i) {
            float q0 = qr[0][i], q1 = qr[1][i], q2 = qr[2][i],
                  q3 = qr[3][i], q4 = qr[4][i];
            #pragma unroll
            for (int dy = 0; dy < 3; ++dy) {
                #pragma unroll
                for (int dx = 0; dx < 3; ++dx) {
                    float vv = vi[(y + dy) * BH + x0 + i + dx];
                    q0 = fmaf(ww[0 * 9 + dy * 3 + dx], vv, q0);
                    q1 = fmaf(ww[1 * 9 + dy * 3 + dx], vv, q1);
                    q2 = fmaf(ww[2 * 9 + dy * 3 + dx], vv, q2);
                    q3 = fmaf(ww[3 * 9 + dy * 3 + dx], vv, q3);
                    q4 = fmaf(ww[4 * 9 + dy * 3 + dx], vv, q4);
                }
            }
            float v = fmaxf(fmaxf(q0, q1), fmaxf(q2, fmaxf(q3, q4)));
            vo[(y + 1) * BH + x0 + i + 1] = v;
        }
        __syncthreads();
    }

    // ---- final q (it=78 even wrote buf[1]) ----
    const float* vi = buf[1];
    const int sx = coords[b * 4 + 0];
    const int sy = coords[b * 4 + 1];
    float* oq = out_q + (size_t)b * 5 * NPIX;

    float qf[5][8];
    #pragma unroll
    for (int i = 0; i < 8; ++i) {
        float q0 = qr[0][i], q1 = qr[1][i], q2 = qr[2][i],
              q3 = qr[3][i], q4 = qr[4][i];
        #pragma unroll
        for (int dy = 0; dy < 3; ++dy) {
            #pragma unroll
            for (int dx = 0; dx < 3; ++dx) {
                float vv = vi[(y + dy) * BH + x0 + i + dx];
                q0 = fmaf(ww[0 * 9 + dy * 3 + dx], vv, q0);
                q1 = fmaf(ww[1 * 9 + dy * 3 + dx], vv, q1);
                q2 = fmaf(ww[2 * 9 + dy * 3 + dx], vv, q2);
                q3 = fmaf(ww[3 * 9 + dy * 3 + dx], vv, q3);
                q4 = fmaf(ww[4 * 9 + dy * 3 + dx], vv, q4);
            }
        }
        qf[0][i] = q0; qf[1][i] = q1; qf[2][i] = q2; qf[3][i] = q3; qf[4][i] = q4;
        if (y == sx && (x0 + i) == sy) {
            out_logits[b * 5 + 0] = q0;
            out_logits[b * 5 + 1] = q1;
            out_logits[b * 5 + 2] = q2;
            out_logits[b * 5 + 3] = q3;
            out_logits[b * 5 + 4] = q4;
        }
    }

    // vectorized, coalesced q stores (each thread owns 8 contiguous floats/row)
    #pragma unroll
    for (int a = 0; a < 5; ++a) {
        float* base = oq + a * NPIX + y * 64 + x0;
        float4 v0 = make_float4(qf[a][0], qf[a][1], qf[a][2], qf[a][3]);
        float4 v1 = make_float4(qf[a][4], qf[a][5], qf[a][6], qf[a][7]);
        *reinterpret_cast<float4*>(base)     = v0;
        *reinterpret_cast<float4*>(base + 4) = v1;
    }
}

extern "C" void kernel_launch(void* const* d_in, const int* in_sizes, int n_in,
                              void* d_out, int out_size) {
    const float* input  = (const float*)d_in[0];
    const int*   coords = (const int*)  d_in[1];
    const float* w_h    = (const float*)d_in[2];
    const float* b_h    = (const float*)d_in[3];
    const float* w_r    = (const float*)d_in[4];
    const float* w_q    = (const float*)d_in[5];
    const float* w_w    = (const float*)d_in[6];
    float* out = (float*)d_out;

    prep_kernel<<<1, 32>>>(w_h, b_h, w_r);
    vin_kernel<<<128, 512>>>(input, coords, w_q, w_w,
                             out, out + 128 * 5 * NPIX);
}